// round 13
// baseline (speedup 1.0000x reference)
#include <cuda_runtime.h>
#include <cstdint>

// Problem constants
#define LL 2
#define BB 16
#define TT 512
#define HH 12
#define NL 4096   // (1+1)^12 leaves
#define NC 1000
#define NCHUNK 16 // token chunks per batch
#define TOKC 32   // tokens per chunk

// GEMM tiling: 256 CTAs = (64 row-chunks) x (4 col-tiles)
#define G_LCH 64
#define G_CTW 256
#define NCTA  256
#define R_STG 16
#define NSTG  (G_LCH / R_STG)

// Scratch + sync counters
__device__ float g_part[NCHUNK * BB * NL];   // [chunk][batch][leaf] (4 MB)
__device__ float g_red[G_LCH ? 64 * BB * NC : 1]; // [split64][b][c] partials (4 MB)
__device__ int gA = 0;   // leaf-done
__device__ int gC = 0;   // gemm-partials-done
__device__ int gB = 0;   // exit ticket (counter reset)

// Dynamic smem layout (bytes)
#define SM_SS 0                     // score tile: 64*256*4 = 65536
#define SM_P  65536                 // leaf products: 32*128*4 = 16384
#define SM_SX 81920                 // x slice: 32*12*4 = 1536
#define SM_SC 83456                 // cuts: 64
#define SM_SA 83520                 // avg tile [l][b]: 64*16*4 = 4096
#define SM_MB 87616                 // mbarriers: 4*8 = 32
#define SMEM_TOTAL 87680

// ---- f32x2 helpers ---------------------------------------------------------
__device__ __forceinline__ unsigned long long pk2(float x, float y) {
    unsigned long long r;
    asm("mov.b64 %0, {%1, %2};" : "=l"(r) : "f"(x), "f"(y));
    return r;
}
__device__ __forceinline__ void fma2(unsigned long long& d,
                                     unsigned long long a,
                                     unsigned long long b) {
    asm("fma.rn.f32x2 %0, %1, %2, %0;" : "+l"(d) : "l"(a), "l"(b));
}
__device__ __forceinline__ void upk2(unsigned long long v, float& lo, float& hi) {
    asm("mov.b64 {%0, %1}, %2;" : "=f"(lo), "=f"(hi) : "l"(v));
}

// ---- smem/TMA/sync helpers -------------------------------------------------
__device__ __forceinline__ uint32_t smem_u32(const void* p) {
    uint32_t a;
    asm("{ .reg .u64 t; cvta.to.shared.u64 t, %1; cvt.u32.u64 %0, t; }"
        : "=r"(a) : "l"(p));
    return a;
}
__device__ __forceinline__ void mbar_init(uint32_t mbar, uint32_t count) {
    asm volatile("mbarrier.init.shared.b64 [%0], %1;" :: "r"(mbar), "r"(count)
                 : "memory");
}
__device__ __forceinline__ void mbar_expect_tx(uint32_t mbar, uint32_t bytes) {
    asm volatile("mbarrier.arrive.expect_tx.shared.b64 _, [%0], %1;"
                 :: "r"(mbar), "r"(bytes) : "memory");
}
__device__ __forceinline__ void mbar_wait(uint32_t mbar, uint32_t parity) {
    uint32_t done;
    asm volatile(
        "{\n\t"
        ".reg .pred p;\n\t"
        "mbarrier.try_wait.parity.acquire.cta.shared::cta.b64 p, [%1], %2;\n\t"
        "selp.b32 %0, 1, 0, p;\n\t"
        "}"
        : "=r"(done) : "r"(mbar), "r"(parity) : "memory");
    if (!done) {
        asm volatile(
            "{\n\t"
            ".reg .pred P1;\n\t"
            "W_%=:\n\t"
            "mbarrier.try_wait.parity.acquire.cta.shared::cta.b64 P1, [%0], %1, 0x989680;\n\t"
            "@P1 bra.uni D_%=;\n\t"
            "bra.uni W_%=;\n\t"
            "D_%=:\n\t"
            "}"
            :: "r"(mbar), "r"(parity) : "memory");
    }
}
__device__ __forceinline__ void bulk_g2s(uint32_t dst, const void* src,
                                         uint32_t bytes, uint32_t mbar) {
    asm volatile(
        "cp.async.bulk.shared::cta.global.mbarrier::complete_tx::bytes "
        "[%0], [%1], %2, [%3];"
        :: "r"(dst), "l"(src), "r"(bytes), "r"(mbar) : "memory");
}
__device__ __forceinline__ int ld_acquire(const int* p) {
    int v;
    asm volatile("ld.acquire.gpu.b32 %0, [%1];" : "=r"(v) : "l"(p));
    return v;
}

// ---------------------------------------------------------------------------
// Fused persistent kernel: 256 CTAs x 256 threads, all co-resident.
// P0: issue staged TMA for this CTA's 64x256 score tile (streams from t=0).
// P1: leaf products -> g_part (overlaps stream).
// B1: grid barrier.
// P2: reduce g_part -> sA; staged GEMM; PLAIN STG partials -> g_red[rc].
// B2: grid barrier.
// P3: final reduction: out[oi] = sum_s g_red[s][oi]  (no atomics anywhere).
// ---------------------------------------------------------------------------
__global__ void __launch_bounds__(256, 2) fused_kernel(
    const float* __restrict__ x, const float* __restrict__ cuts,
    const float* __restrict__ score, float* __restrict__ out)
{
    extern __shared__ __align__(16) char sm[];
    float* sS = (float*)(sm + SM_SS);
    float* P  = (float*)(sm + SM_P);
    float* sx = (float*)(sm + SM_SX);
    float* sc = (float*)(sm + SM_SC);
    float* sA = (float*)(sm + SM_SA);
    const uint32_t mb0 = smem_u32(sm + SM_MB);

    const int tid = threadIdx.x;
    const int blk = blockIdx.x;

    // GEMM tile coordinates
    const int rc = blk >> 2;                    // row-chunk = split index
    const int l0 = rc * G_LCH;
    const int c0 = (blk & 3) * G_CTW;
    const int wbytes = (c0 + G_CTW <= NC) ? (G_CTW * 4) : ((NC - c0) * 4);

    // ---- P0: init mbarriers, then issue 4 TMA stages in parallel ----
    if (tid == 0) {
#pragma unroll
        for (int s = 0; s < NSTG; s++) mbar_init(mb0 + 8 * s, 1);
        asm volatile("fence.proxy.async.shared::cta;" ::: "memory");
    }
    __syncthreads();

    if (tid < NSTG) {
        const int s = tid;
        const uint32_t mb = mb0 + 8 * s;
        mbar_expect_tx(mb, (uint32_t)(R_STG * wbytes));
        const char* src = (const char*)score
            + (size_t)(l0 + s * R_STG) * (NC * 4) + (size_t)c0 * 4;
        const uint32_t dstb = smem_u32(sS) + (uint32_t)(s * R_STG * G_CTW * 4);
#pragma unroll
        for (int r = 0; r < R_STG; r++)
            bulk_g2s(dstb + (uint32_t)(r * G_CTW * 4),
                     src + (size_t)r * (NC * 4), (uint32_t)wbytes, mb);
    }

    // ---- P1: leaf products ----
    {
        const int b     = blk >> 4;
        const int chunk = blk & 15;

        if (tid < 12) sc[tid] = cuts[tid];
        const float* xl = x + (size_t)(LL - 1) * BB * TT * HH
                            + ((size_t)b * TT + (size_t)chunk * TOKC) * HH;
        for (int i = tid; i < TOKC * 12; i += 256) sx[i] = xl[i];
        __syncthreads();

        // Phase A: factorized half-leaf products
        {
            const int half = (tid >> 3) & 1;
            const int g    = tid & 7;
            const float* cr = sc + half * 6;
            const float c0f = cr[0], c1f = cr[1], c2f = cr[2];
            const float c3f = cr[3], c4f = cr[4], c5f = cr[5];
#pragma unroll
            for (int t2 = 0; t2 < 2; t2++) {
                const int tok = (tid >> 4) + t2 * 16;
                const float* xr = sx + tok * 12 + half * 6;
                const float x0 = xr[0], x1 = xr[1], x2 = xr[2];
                const float x3 = xr[3], x4 = xr[4], x5 = xr[5];
                const float F0 = (g & 4) ? fmaf(2.f, x0, -c0f) : x0;
                const float F1 = (g & 2) ? fmaf(2.f, x1, -c1f) : x1;
                const float F2 = (g & 1) ? fmaf(2.f, x2, -c2f) : x2;
                const float p  = F0 * F1 * F2;
                const float b3 = fmaf(2.f, x3, -c3f);
                const float a4 = x4, b4 = fmaf(2.f, x4, -c4f);
                const float a5 = x5, b5 = fmaf(2.f, x5, -c5f);
                const float m00 = a4 * a5, m01 = a4 * b5;
                const float m10 = b4 * a5, m11 = b4 * b5;
                const float q0 = p * x3, q1 = p * b3;
                float* dst = P + tok * 128 + half * 64 + g * 8;
                *(float4*)dst       = make_float4(q0 * m00, q0 * m01, q0 * m10, q0 * m11);
                *(float4*)(dst + 4) = make_float4(q1 * m00, q1 * m01, q1 * m10, q1 * m11);
            }
        }
        __syncthreads();

        // Phase B: rank-1 accumulation into g_part
        {
            const int w = tid >> 5, lane = tid & 31;
            unsigned long long acc2[4][2];
#pragma unroll
            for (int p = 0; p < 4; p++) { acc2[p][0] = 0ull; acc2[p][1] = 0ull; }

#pragma unroll 4
            for (int tok = 0; tok < TOKC; tok++) {
                const float* Pr = P + tok * 128;
                const ulonglong2* ph = (const ulonglong2*)(Pr + 8 * w);
                const ulonglong2 h0 = ph[0];
                const ulonglong2 h1 = ph[1];
                const float plo0 = Pr[64 + lane];
                const float plo1 = Pr[64 + lane + 32];
                const unsigned long long pl0 = pk2(plo0, plo0);
                const unsigned long long pl1 = pk2(plo1, plo1);
                fma2(acc2[0][0], h0.x, pl0); fma2(acc2[0][1], h0.x, pl1);
                fma2(acc2[1][0], h0.y, pl0); fma2(acc2[1][1], h0.y, pl1);
                fma2(acc2[2][0], h1.x, pl0); fma2(acc2[2][1], h1.x, pl1);
                fma2(acc2[3][0], h1.y, pl0); fma2(acc2[3][1], h1.y, pl1);
            }

            const float s = 1.f / (float)TT;
            float* dst = g_part + ((size_t)(chunk * BB + b)) * NL;
#pragma unroll
            for (int p = 0; p < 4; p++) {
                float u0v0, u1v0, u0v1, u1v1;
                upk2(acc2[p][0], u0v0, u1v0);
                upk2(acc2[p][1], u0v1, u1v1);
                const int u0 = 8 * w + 2 * p;
                dst[u0 * 64 + lane]            = u0v0 * s;
                dst[u0 * 64 + lane + 32]       = u0v1 * s;
                dst[(u0 + 1) * 64 + lane]      = u1v0 * s;
                dst[(u0 + 1) * 64 + lane + 32] = u1v1 * s;
            }
        }
    }

    // ---- B1: grid barrier ----
    __threadfence();
    __syncthreads();
    if (tid == 0) {
        atomicAdd(&gA, 1);
        while (ld_acquire(&gA) < NCTA) { __nanosleep(64); }
    }
    __syncthreads();

    // ---- P2a: reduce 16 chunk partials -> sA[l][b] (L2-hot) ----
    {
        const int bb = tid >> 4;
        const int lq = tid & 15;
        const float4* p = (const float4*)(g_part + (size_t)bb * NL + l0) + lq;
        float4 v = make_float4(0.f, 0.f, 0.f, 0.f);
#pragma unroll
        for (int ch = 0; ch < NCHUNK; ch++) {
            const float4 t = p[(size_t)ch * (BB * NL / 4)];
            v.x += t.x; v.y += t.y; v.z += t.z; v.w += t.w;
        }
        sA[(lq * 4 + 0) * 16 + bb] = v.x;
        sA[(lq * 4 + 1) * 16 + bb] = v.y;
        sA[(lq * 4 + 2) * 16 + bb] = v.z;
        sA[(lq * 4 + 3) * 16 + bb] = v.w;
    }
    __syncthreads();

    // ---- P2b: staged GEMM; plain STG partials into g_red[rc] ----
    {
        unsigned long long acc[8];
#pragma unroll
        for (int p = 0; p < 8; p++) acc[p] = 0ull;

        const int c = c0 + tid;
        const float* sSs = sS + tid;

#pragma unroll
        for (int s = 0; s < NSTG; s++) {
            mbar_wait(mb0 + 8 * s, 0);
            const float* sAs = sA + (s * R_STG) * 16;
#pragma unroll
            for (int r = 0; r < R_STG; r++) {
                const float sv = sSs[(s * R_STG + r) * G_CTW];
                const unsigned long long ss = pk2(sv, sv);
                const ulonglong2* ar = (const ulonglong2*)(sAs + r * 16);
                const ulonglong2 q0 = ar[0];
                const ulonglong2 q1 = ar[1];
                fma2(acc[0], ss, q0.x); fma2(acc[1], ss, q0.y);
                fma2(acc[2], ss, q1.x); fma2(acc[3], ss, q1.y);
                const ulonglong2 q2 = ar[2];
                const ulonglong2 q3 = ar[3];
                fma2(acc[4], ss, q2.x); fma2(acc[5], ss, q2.y);
                fma2(acc[6], ss, q3.x); fma2(acc[7], ss, q3.y);
            }
        }

        if (c < NC) {
            float* dst = g_red + (size_t)rc * (BB * NC) + c;
#pragma unroll
            for (int p = 0; p < 8; p++) {
                float blo, bhi;
                upk2(acc[p], blo, bhi);
                dst[(2 * p) * NC]     = blo;
                dst[(2 * p + 1) * NC] = bhi;
            }
        }
    }

    // ---- B2: grid barrier ----
    __threadfence();
    __syncthreads();
    if (tid == 0) {
        atomicAdd(&gC, 1);
        while (ld_acquire(&gC) < NCTA) { __nanosleep(64); }
    }
    __syncthreads();

    // ---- P3: final reduce — 4 threads per output, 16 splits each ----
    {
        const int oi = blk * 64 + (tid >> 2);     // output index [b*1000+c]
        const int s0 = (tid & 3) * 16;
        float v = 0.f;
        if (oi < BB * NC) {
            const float* p = g_red + (size_t)s0 * (BB * NC) + oi;
#pragma unroll
            for (int k = 0; k < 16; k++)
                v += p[(size_t)k * (BB * NC)];
        }
        v += __shfl_xor_sync(0xFFFFFFFFu, v, 1);
        v += __shfl_xor_sync(0xFFFFFFFFu, v, 2);
        if ((tid & 3) == 0 && oi < BB * NC) out[oi] = v;
    }

    // ---- Reset counters for next graph replay ----
    __syncthreads();
    if (tid == 0) {
        const int t = atomicAdd(&gB, 1);
        if (t == NCTA - 1) {
            atomicExch(&gB, 0);
            atomicExch(&gA, 0);
            atomicExch(&gC, 0);
        }
    }
}

// ---------------------------------------------------------------------------
extern "C" void kernel_launch(void* const* d_in, const int* in_sizes, int n_in,
                              void* d_out, int out_size)
{
    const float* x     = (const float*)d_in[0];  // (2,16,512,12)
    const float* cuts  = (const float*)d_in[1];  // (12,1)
    const float* score = (const float*)d_in[2];  // (4096,1000)
    float* out = (float*)d_out;                  // (16,1000)

    static bool attr_set = false;
    if (!attr_set) {
        cudaFuncSetAttribute(fused_kernel,
                             cudaFuncAttributeMaxDynamicSharedMemorySize,
                             SMEM_TOTAL);
        attr_set = true;
    }
    fused_kernel<<<NCTA, 256, SMEM_TOTAL>>>(x, cuts, score, out);
}

// round 14
// speedup vs baseline: 1.0917x; 1.0917x over previous
#include <cuda_runtime.h>
#include <cstdint>

// Problem constants
#define LL 2
#define BB 16
#define TT 512
#define HH 12
#define NL 4096   // (1+1)^12 leaves
#define NC 1000
#define NCHUNK 16 // token chunks per batch
#define TOKC 32   // tokens per chunk

// Scratch
__device__ float g_part[NCHUNK * BB * NL];  // [chunk][batch][leaf] (4 MB)
__device__ float g_avg[BB * NL];            // [batch][leaf] (256 KB)

// ---- f32x2 helpers ---------------------------------------------------------
__device__ __forceinline__ unsigned long long pk2(float x, float y) {
    unsigned long long r;
    asm("mov.b64 %0, {%1, %2};" : "=l"(r) : "f"(x), "f"(y));
    return r;
}
__device__ __forceinline__ void fma2(unsigned long long& d,
                                     unsigned long long a,
                                     unsigned long long b) {
    asm("fma.rn.f32x2 %0, %1, %2, %0;" : "+l"(d) : "l"(a), "l"(b));
}
__device__ __forceinline__ void upk2(unsigned long long v, float& lo, float& hi) {
    asm("mov.b64 {%0, %1}, %2;" : "=f"(lo), "=f"(hi) : "l"(v));
}

// ---- cp.async helpers ------------------------------------------------------
__device__ __forceinline__ uint32_t smem_u32(const void* p) {
    uint32_t a;
    asm("{ .reg .u64 t; cvta.to.shared.u64 t, %1; cvt.u32.u64 %0, t; }"
        : "=r"(a) : "l"(p));
    return a;
}
__device__ __forceinline__ void cp_async16(uint32_t dst, const void* src, int sz) {
    asm volatile("cp.async.cg.shared.global [%0], [%1], 16, %2;"
                 :: "r"(dst), "l"(src), "r"(sz));
}
__device__ __forceinline__ void cp_commit() {
    asm volatile("cp.async.commit_group;");
}
template <int N> __device__ __forceinline__ void cp_wait() {
    asm volatile("cp.async.wait_group %0;" :: "n"(N));
}

// ---------------------------------------------------------------------------
// Kernel 1: per-(batch, token-chunk) partial mean-leaf vectors, disjoint STG.
// grid = B * NCHUNK = 256 blocks, 256 threads. Also zeroes `out`.
// (R6 factorized version — measured fast.)
// ---------------------------------------------------------------------------
__global__ __launch_bounds__(256) void leaf_kernel(
    const float* __restrict__ x, const float* __restrict__ cuts,
    float* __restrict__ out)
{
    const int tid = threadIdx.x;
    const int gid = blockIdx.x * 256 + tid;    // 65536 >= 16000
    if (gid < BB * NC) out[gid] = 0.f;

    const int b     = blockIdx.x >> 4;
    const int chunk = blockIdx.x & 15;

    __shared__ float P[TOKC * 128];            // [tok][half*64 + u]  (16 KB)
    __shared__ float sx[TOKC * 12];
    __shared__ float sc[12];

    if (tid < 12) sc[tid] = cuts[tid];

    const float* xl = x + (size_t)(LL - 1) * BB * TT * HH
                        + ((size_t)b * TT + (size_t)chunk * TOKC) * HH;
    for (int i = tid; i < TOKC * 12; i += 256) sx[i] = xl[i];
    __syncthreads();

    // Phase A: factorized half-leaf products (8 contiguous outputs per task)
    {
        const int half = (tid >> 3) & 1;
        const int g    = tid & 7;
        const float* cr = sc + half * 6;
        const float c0 = cr[0], c1 = cr[1], c2 = cr[2];
        const float c3 = cr[3], c4 = cr[4], c5 = cr[5];
#pragma unroll
        for (int t2 = 0; t2 < 2; t2++) {
            const int tok = (tid >> 4) + t2 * 16;
            const float* xr = sx + tok * 12 + half * 6;
            const float x0 = xr[0], x1 = xr[1], x2 = xr[2];
            const float x3 = xr[3], x4 = xr[4], x5 = xr[5];
            const float F0 = (g & 4) ? fmaf(2.f, x0, -c0) : x0;
            const float F1 = (g & 2) ? fmaf(2.f, x1, -c1) : x1;
            const float F2 = (g & 1) ? fmaf(2.f, x2, -c2) : x2;
            const float p  = F0 * F1 * F2;
            const float b3 = fmaf(2.f, x3, -c3);
            const float a4 = x4, b4 = fmaf(2.f, x4, -c4);
            const float a5 = x5, b5 = fmaf(2.f, x5, -c5);
            const float m00 = a4 * a5, m01 = a4 * b5;
            const float m10 = b4 * a5, m11 = b4 * b5;
            const float q0 = p * x3, q1 = p * b3;
            float* dst = P + tok * 128 + half * 64 + g * 8;
            *(float4*)dst       = make_float4(q0 * m00, q0 * m01, q0 * m10, q0 * m11);
            *(float4*)(dst + 4) = make_float4(q1 * m00, q1 * m01, q1 * m10, q1 * m11);
        }
    }
    __syncthreads();

    // Phase B: rank-1 accumulation
    const int w = tid >> 5, lane = tid & 31;
    unsigned long long acc2[4][2];
#pragma unroll
    for (int p = 0; p < 4; p++) { acc2[p][0] = 0ull; acc2[p][1] = 0ull; }

#pragma unroll 4
    for (int tok = 0; tok < TOKC; tok++) {
        const float* Pr = P + tok * 128;
        const ulonglong2* ph = (const ulonglong2*)(Pr + 8 * w);
        const ulonglong2 h0 = ph[0];
        const ulonglong2 h1 = ph[1];
        const float plo0 = Pr[64 + lane];
        const float plo1 = Pr[64 + lane + 32];
        const unsigned long long pl0 = pk2(plo0, plo0);
        const unsigned long long pl1 = pk2(plo1, plo1);
        fma2(acc2[0][0], h0.x, pl0); fma2(acc2[0][1], h0.x, pl1);
        fma2(acc2[1][0], h0.y, pl0); fma2(acc2[1][1], h0.y, pl1);
        fma2(acc2[2][0], h1.x, pl0); fma2(acc2[2][1], h1.x, pl1);
        fma2(acc2[3][0], h1.y, pl0); fma2(acc2[3][1], h1.y, pl1);
    }

    const float s = 1.f / (float)TT;
    float* dst = g_part + ((size_t)(chunk * BB + b)) * NL;
#pragma unroll
    for (int p = 0; p < 4; p++) {
        float u0v0, u1v0, u0v1, u1v1;
        upk2(acc2[p][0], u0v0, u1v0);
        upk2(acc2[p][1], u0v1, u1v1);
        const int u0 = 8 * w + 2 * p;
        dst[u0 * 64 + lane]            = u0v0 * s;
        dst[u0 * 64 + lane + 32]       = u0v1 * s;
        dst[(u0 + 1) * 64 + lane]      = u1v0 * s;
        dst[(u0 + 1) * 64 + lane + 32] = u1v1 * s;
    }
}

// ---------------------------------------------------------------------------
// Kernel 2: reduce the 16 chunk partials -> g_avg[16][4096]. 4 MB read, float4.
// ---------------------------------------------------------------------------
__global__ __launch_bounds__(256) void reduce_kernel()
{
    const int i4 = blockIdx.x * 256 + threadIdx.x;   // 0 .. 16383 (float4 id)
    const float4* src = (const float4*)g_part + i4;
    float4 v = make_float4(0.f, 0.f, 0.f, 0.f);
#pragma unroll
    for (int ch = 0; ch < NCHUNK; ch++) {
        const float4 t = src[(size_t)ch * (BB * NL / 4)];
        v.x += t.x; v.y += t.y; v.z += t.z; v.w += t.w;
    }
    ((float4*)g_avg)[i4] = v;
}

// ---------------------------------------------------------------------------
// Kernel 3: out[16,1000] += g_avg[16,4096] @ score[4096,1000].
// grid = (64, 8), 128 threads. LCHUNK=64 rows, CTILE=128 cols.
// 4-stage up-front cp.async (8 KB/stage, 32 KB in flight), ~6 CTAs/SM.
// Thread owns 1 column x all 16 batches (8 packed f32x2 accumulators).
// (R4 version — reconstructed-fast.)
// ---------------------------------------------------------------------------
#define G_LCH  64
#define G_CT   128
#define SROWS  16   // rows per pipeline stage
#define NSTAGE 4

__global__ __launch_bounds__(128) void gemm_out_kernel(
    const float* __restrict__ score, float* __restrict__ out)
{
    __shared__ float sS[G_LCH * G_CT];   // 32 KB score tile (4 stages x 16 rows)
    __shared__ float sA[G_LCH * 16];     // 4 KB  [l][b]

    const int tid = threadIdx.x;
    const int l0  = blockIdx.x * G_LCH;
    const int c0  = blockIdx.y * G_CT;
    const uint32_t sS_base = smem_u32(sS);

    // Issue all 4 stages of async score loads up front (32 KB in flight).
#pragma unroll
    for (int s = 0; s < NSTAGE; s++) {
#pragma unroll
        for (int t = 0; t < 4; t++) {
            const int k  = tid + t * 128;           // 0..511 chunk id
            const int r  = k >> 5;                  // row within stage 0..15
            const int cc = k & 31;                  // 16B chunk within row
            const int col = c0 + cc * 4;
            const char* src = (const char*)score
                + (size_t)(l0 + s * SROWS + r) * (NC * 4) + (size_t)col * 4;
            const uint32_t dst = sS_base
                + (uint32_t)(((s * SROWS + r) * G_CT + cc * 4) * 4);
            const int sz = (col + 4 <= NC) ? 16 : 0;
            cp_async16(dst, src, sz);
        }
        cp_commit();
    }

    // Build sA from g_avg (L2-hot, 4 KB per block) while loads fly.
    for (int e = tid; e < 16 * G_LCH; e += 128) {
        const int bb = e >> 6;
        const int l  = e & (G_LCH - 1);
        sA[l * 16 + bb] = g_avg[bb * NL + l0 + l];
    }

    unsigned long long acc[8];
#pragma unroll
    for (int p = 0; p < 8; p++) acc[p] = 0ull;

    const int c = c0 + tid;

    // Consume stages
#pragma unroll
    for (int s = 0; s < NSTAGE; s++) {
        if (s == 0) cp_wait<3>();
        else if (s == 1) cp_wait<2>();
        else if (s == 2) cp_wait<1>();
        else cp_wait<0>();
        __syncthreads();

#pragma unroll
        for (int r = 0; r < SROWS; r++) {
            const int l = s * SROWS + r;
            const float sv = sS[l * G_CT + tid];
            const unsigned long long ss = pk2(sv, sv);
            const ulonglong2* ar = (const ulonglong2*)(sA + l * 16);
            const ulonglong2 q0 = ar[0];
            const ulonglong2 q1 = ar[1];
            const ulonglong2 q2 = ar[2];
            const ulonglong2 q3 = ar[3];
            fma2(acc[0], ss, q0.x); fma2(acc[1], ss, q0.y);
            fma2(acc[2], ss, q1.x); fma2(acc[3], ss, q1.y);
            fma2(acc[4], ss, q2.x); fma2(acc[5], ss, q2.y);
            fma2(acc[6], ss, q3.x); fma2(acc[7], ss, q3.y);
        }
    }

    if (c < NC) {
#pragma unroll
        for (int p = 0; p < 8; p++) {
            float blo, bhi;
            upk2(acc[p], blo, bhi);
            atomicAdd(out + (2 * p) * NC + c,     blo);
            atomicAdd(out + (2 * p + 1) * NC + c, bhi);
        }
    }
}

// ---------------------------------------------------------------------------
extern "C" void kernel_launch(void* const* d_in, const int* in_sizes, int n_in,
                              void* d_out, int out_size)
{
    const float* x     = (const float*)d_in[0];  // (2,16,512,12)
    const float* cuts  = (const float*)d_in[1];  // (12,1)
    const float* score = (const float*)d_in[2];  // (4096,1000)
    float* out = (float*)d_out;                  // (16,1000)

    leaf_kernel<<<BB * NCHUNK, 256>>>(x, cuts, out);
    reduce_kernel<<<BB * NL / (256 * 4), 256>>>();
    dim3 g3(NL / G_LCH, (NC + G_CT - 1) / G_CT);   // (64, 8)
    gemm_out_kernel<<<g3, 128>>>(score, out);
}

// round 15
// speedup vs baseline: 1.0935x; 1.0017x over previous
#include <cuda_runtime.h>
#include <cstdint>

// Problem constants
#define LL 2
#define BB 16
#define TT 512
#define HH 12
#define NL 4096   // (1+1)^12 leaves
#define NC 1000
#define NCHUNK 16 // token chunks per batch
#define TOKC 32   // tokens per chunk

// Scratch
__device__ float g_part[NCHUNK * BB * NL];  // [chunk][batch][leaf] (4 MB)
__device__ float g_avg[BB * NL];            // [batch][leaf] (256 KB)

// ---- f32x2 helpers ---------------------------------------------------------
__device__ __forceinline__ unsigned long long pk2(float x, float y) {
    unsigned long long r;
    asm("mov.b64 %0, {%1, %2};" : "=l"(r) : "f"(x), "f"(y));
    return r;
}
__device__ __forceinline__ void fma2(unsigned long long& d,
                                     unsigned long long a,
                                     unsigned long long b) {
    asm("fma.rn.f32x2 %0, %1, %2, %0;" : "+l"(d) : "l"(a), "l"(b));
}
__device__ __forceinline__ void upk2(unsigned long long v, float& lo, float& hi) {
    asm("mov.b64 {%0, %1}, %2;" : "=f"(lo), "=f"(hi) : "l"(v));
}

// ---- cp.async helpers ------------------------------------------------------
__device__ __forceinline__ uint32_t smem_u32(const void* p) {
    uint32_t a;
    asm("{ .reg .u64 t; cvta.to.shared.u64 t, %1; cvt.u32.u64 %0, t; }"
        : "=r"(a) : "l"(p));
    return a;
}
__device__ __forceinline__ void cp_async16(uint32_t dst, const void* src, int sz) {
    asm volatile("cp.async.cg.shared.global [%0], [%1], 16, %2;"
                 :: "r"(dst), "l"(src), "r"(sz));
}
__device__ __forceinline__ void cp_commit() {
    asm volatile("cp.async.commit_group;");
}
template <int N> __device__ __forceinline__ void cp_wait() {
    asm volatile("cp.async.wait_group %0;" :: "n"(N));
}

// ---------------------------------------------------------------------------
// Kernel 1: per-(batch, token-chunk) partial mean-leaf vectors, disjoint STG.
// grid = B * NCHUNK = 256 blocks, 256 threads. Also zeroes `out`.
// Phase B software-pipelined: 2-token batches, loads hoisted, full unroll.
// ---------------------------------------------------------------------------
__global__ __launch_bounds__(256) void leaf_kernel(
    const float* __restrict__ x, const float* __restrict__ cuts,
    float* __restrict__ out)
{
    const int tid = threadIdx.x;
    const int gid = blockIdx.x * 256 + tid;    // 65536 >= 16000
    if (gid < BB * NC) out[gid] = 0.f;

    const int b     = blockIdx.x >> 4;
    const int chunk = blockIdx.x & 15;

    __shared__ float P[TOKC * 128];            // [tok][half*64 + u]  (16 KB)
    __shared__ float sx[TOKC * 12];
    __shared__ float sc[12];

    if (tid < 12) sc[tid] = cuts[tid];

    const float* xl = x + (size_t)(LL - 1) * BB * TT * HH
                        + ((size_t)b * TT + (size_t)chunk * TOKC) * HH;
    for (int i = tid; i < TOKC * 12; i += 256) sx[i] = xl[i];
    __syncthreads();

    // Phase A: factorized half-leaf products (8 contiguous outputs per task)
    {
        const int half = (tid >> 3) & 1;
        const int g    = tid & 7;
        const float* cr = sc + half * 6;
        const float c0 = cr[0], c1 = cr[1], c2 = cr[2];
        const float c3 = cr[3], c4 = cr[4], c5 = cr[5];
#pragma unroll
        for (int t2 = 0; t2 < 2; t2++) {
            const int tok = (tid >> 4) + t2 * 16;
            const float* xr = sx + tok * 12 + half * 6;
            const float x0 = xr[0], x1 = xr[1], x2 = xr[2];
            const float x3 = xr[3], x4 = xr[4], x5 = xr[5];
            const float F0 = (g & 4) ? fmaf(2.f, x0, -c0) : x0;
            const float F1 = (g & 2) ? fmaf(2.f, x1, -c1) : x1;
            const float F2 = (g & 1) ? fmaf(2.f, x2, -c2) : x2;
            const float p  = F0 * F1 * F2;
            const float b3 = fmaf(2.f, x3, -c3);
            const float a4 = x4, b4 = fmaf(2.f, x4, -c4);
            const float a5 = x5, b5 = fmaf(2.f, x5, -c5);
            const float m00 = a4 * a5, m01 = a4 * b5;
            const float m10 = b4 * a5, m11 = b4 * b5;
            const float q0 = p * x3, q1 = p * b3;
            float* dst = P + tok * 128 + half * 64 + g * 8;
            *(float4*)dst       = make_float4(q0 * m00, q0 * m01, q0 * m10, q0 * m11);
            *(float4*)(dst + 4) = make_float4(q1 * m00, q1 * m01, q1 * m10, q1 * m11);
        }
    }
    __syncthreads();

    // Phase B: rank-1 accumulation, software-pipelined in 2-token batches.
    // All 8 shared loads of a batch are issued before any compute; full
    // unroll lets ptxas overlap LDS latency across batches.
    const int w = tid >> 5, lane = tid & 31;
    unsigned long long acc2[4][2];
#pragma unroll
    for (int p = 0; p < 4; p++) { acc2[p][0] = 0ull; acc2[p][1] = 0ull; }

#pragma unroll
    for (int tok = 0; tok < TOKC; tok += 2) {
        const float* Pr0 = P + tok * 128;
        const float* Pr1 = Pr0 + 128;
        // Batched loads (8 LDS in flight)
        const ulonglong2 h00 = *(const ulonglong2*)(Pr0 + 8 * w);
        const ulonglong2 h01 = *(const ulonglong2*)(Pr0 + 8 * w + 4);
        const ulonglong2 h10 = *(const ulonglong2*)(Pr1 + 8 * w);
        const ulonglong2 h11 = *(const ulonglong2*)(Pr1 + 8 * w + 4);
        const float pa0 = Pr0[64 + lane];
        const float pa1 = Pr0[96 + lane];
        const float pb0 = Pr1[64 + lane];
        const float pb1 = Pr1[96 + lane];

        const unsigned long long A0 = pk2(pa0, pa0);
        const unsigned long long A1 = pk2(pa1, pa1);
        const unsigned long long B0 = pk2(pb0, pb0);
        const unsigned long long B1 = pk2(pb1, pb1);

        // token tok
        fma2(acc2[0][0], h00.x, A0); fma2(acc2[0][1], h00.x, A1);
        fma2(acc2[1][0], h00.y, A0); fma2(acc2[1][1], h00.y, A1);
        fma2(acc2[2][0], h01.x, A0); fma2(acc2[2][1], h01.x, A1);
        fma2(acc2[3][0], h01.y, A0); fma2(acc2[3][1], h01.y, A1);
        // token tok+1
        fma2(acc2[0][0], h10.x, B0); fma2(acc2[0][1], h10.x, B1);
        fma2(acc2[1][0], h10.y, B0); fma2(acc2[1][1], h10.y, B1);
        fma2(acc2[2][0], h11.x, B0); fma2(acc2[2][1], h11.x, B1);
        fma2(acc2[3][0], h11.y, B0); fma2(acc2[3][1], h11.y, B1);
    }

    const float s = 1.f / (float)TT;
    float* dst = g_part + ((size_t)(chunk * BB + b)) * NL;
#pragma unroll
    for (int p = 0; p < 4; p++) {
        float u0v0, u1v0, u0v1, u1v1;
        upk2(acc2[p][0], u0v0, u1v0);
        upk2(acc2[p][1], u0v1, u1v1);
        const int u0 = 8 * w + 2 * p;
        dst[u0 * 64 + lane]            = u0v0 * s;
        dst[u0 * 64 + lane + 32]       = u0v1 * s;
        dst[(u0 + 1) * 64 + lane]      = u1v0 * s;
        dst[(u0 + 1) * 64 + lane + 32] = u1v1 * s;
    }
}

// ---------------------------------------------------------------------------
// Kernel 2: reduce the 16 chunk partials -> g_avg[16][4096]. 4 MB read, float4.
// ---------------------------------------------------------------------------
__global__ __launch_bounds__(256) void reduce_kernel()
{
    const int i4 = blockIdx.x * 256 + threadIdx.x;   // 0 .. 16383 (float4 id)
    const float4* src = (const float4*)g_part + i4;
    float4 v = make_float4(0.f, 0.f, 0.f, 0.f);
#pragma unroll
    for (int ch = 0; ch < NCHUNK; ch++) {
        const float4 t = src[(size_t)ch * (BB * NL / 4)];
        v.x += t.x; v.y += t.y; v.z += t.z; v.w += t.w;
    }
    ((float4*)g_avg)[i4] = v;
}

// ---------------------------------------------------------------------------
// Kernel 3: out[16,1000] += g_avg[16,4096] @ score[4096,1000].
// grid = (64, 8), 128 threads. 4-stage up-front cp.async (32 KB in flight).
// Thread owns 1 column x all 16 batches (8 packed f32x2 accumulators).
// ---------------------------------------------------------------------------
#define G_LCH  64
#define G_CT   128
#define SROWS  16   // rows per pipeline stage
#define NSTAGE 4

__global__ __launch_bounds__(128) void gemm_out_kernel(
    const float* __restrict__ score, float* __restrict__ out)
{
    __shared__ float sS[G_LCH * G_CT];   // 32 KB score tile
    __shared__ float sA[G_LCH * 16];     // 4 KB  [l][b]

    const int tid = threadIdx.x;
    const int l0  = blockIdx.x * G_LCH;
    const int c0  = blockIdx.y * G_CT;
    const uint32_t sS_base = smem_u32(sS);

#pragma unroll
    for (int s = 0; s < NSTAGE; s++) {
#pragma unroll
        for (int t = 0; t < 4; t++) {
            const int k  = tid + t * 128;           // 0..511 chunk id
            const int r  = k >> 5;                  // row within stage 0..15
            const int cc = k & 31;                  // 16B chunk within row
            const int col = c0 + cc * 4;
            const char* src = (const char*)score
                + (size_t)(l0 + s * SROWS + r) * (NC * 4) + (size_t)col * 4;
            const uint32_t dst = sS_base
                + (uint32_t)(((s * SROWS + r) * G_CT + cc * 4) * 4);
            const int sz = (col + 4 <= NC) ? 16 : 0;
            cp_async16(dst, src, sz);
        }
        cp_commit();
    }

    // Build sA from g_avg (L2-hot, 4 KB per block) while loads fly.
    for (int e = tid; e < 16 * G_LCH; e += 128) {
        const int bb = e >> 6;
        const int l  = e & (G_LCH - 1);
        sA[l * 16 + bb] = g_avg[bb * NL + l0 + l];
    }

    unsigned long long acc[8];
#pragma unroll
    for (int p = 0; p < 8; p++) acc[p] = 0ull;

    const int c = c0 + tid;

#pragma unroll
    for (int s = 0; s < NSTAGE; s++) {
        if (s == 0) cp_wait<3>();
        else if (s == 1) cp_wait<2>();
        else if (s == 2) cp_wait<1>();
        else cp_wait<0>();
        __syncthreads();

#pragma unroll
        for (int r = 0; r < SROWS; r++) {
            const int l = s * SROWS + r;
            const float sv = sS[l * G_CT + tid];
            const unsigned long long ss = pk2(sv, sv);
            const ulonglong2* ar = (const ulonglong2*)(sA + l * 16);
            const ulonglong2 q0 = ar[0];
            const ulonglong2 q1 = ar[1];
            const ulonglong2 q2 = ar[2];
            const ulonglong2 q3 = ar[3];
            fma2(acc[0], ss, q0.x); fma2(acc[1], ss, q0.y);
            fma2(acc[2], ss, q1.x); fma2(acc[3], ss, q1.y);
            fma2(acc[4], ss, q2.x); fma2(acc[5], ss, q2.y);
            fma2(acc[6], ss, q3.x); fma2(acc[7], ss, q3.y);
        }
    }

    if (c < NC) {
#pragma unroll
        for (int p = 0; p < 8; p++) {
            float blo, bhi;
            upk2(acc[p], blo, bhi);
            atomicAdd(out + (2 * p) * NC + c,     blo);
            atomicAdd(out + (2 * p + 1) * NC + c, bhi);
        }
    }
}

// ---------------------------------------------------------------------------
extern "C" void kernel_launch(void* const* d_in, const int* in_sizes, int n_in,
                              void* d_out, int out_size)
{
    const float* x     = (const float*)d_in[0];  // (2,16,512,12)
    const float* cuts  = (const float*)d_in[1];  // (12,1)
    const float* score = (const float*)d_in[2];  // (4096,1000)
    float* out = (float*)d_out;                  // (16,1000)

    leaf_kernel<<<BB * NCHUNK, 256>>>(x, cuts, out);
    reduce_kernel<<<BB * NL / (256 * 4), 256>>>();
    dim3 g3(NL / G_LCH, (NC + G_CT - 1) / G_CT);   // (64, 8)
    gemm_out_kernel<<<g3, 128>>>(score, out);
}

// round 16
// speedup vs baseline: 1.1064x; 1.0118x over previous
#include <cuda_runtime.h>
#include <cstdint>

// Problem constants
#define LL 2
#define BB 16
#define TT 512
#define HH 12
#define NL 4096   // (1+1)^12 leaves
#define NC 1000
#define NCHUNK 16 // token chunks per batch
#define TOKC 32   // tokens per chunk

// Scratch: [chunk][batch][leaf]  (4 MB)
__device__ float g_part[NCHUNK * BB * NL];

// ---- f32x2 helpers ---------------------------------------------------------
__device__ __forceinline__ unsigned long long pk2(float x, float y) {
    unsigned long long r;
    asm("mov.b64 %0, {%1, %2};" : "=l"(r) : "f"(x), "f"(y));
    return r;
}
__device__ __forceinline__ void fma2(unsigned long long& d,
                                     unsigned long long a,
                                     unsigned long long b) {
    asm("fma.rn.f32x2 %0, %1, %2, %0;" : "+l"(d) : "l"(a), "l"(b));
}
__device__ __forceinline__ void upk2(unsigned long long v, float& lo, float& hi) {
    asm("mov.b64 {%0, %1}, %2;" : "=f"(lo), "=f"(hi) : "l"(v));
}

// ---- cp.async helpers ------------------------------------------------------
__device__ __forceinline__ uint32_t smem_u32(const void* p) {
    uint32_t a;
    asm("{ .reg .u64 t; cvta.to.shared.u64 t, %1; cvt.u32.u64 %0, t; }"
        : "=r"(a) : "l"(p));
    return a;
}
__device__ __forceinline__ void cp_async16(uint32_t dst, const void* src, int sz) {
    asm volatile("cp.async.cg.shared.global [%0], [%1], 16, %2;"
                 :: "r"(dst), "l"(src), "r"(sz));
}
__device__ __forceinline__ void cp_commit() {
    asm volatile("cp.async.commit_group;");
}
template <int N> __device__ __forceinline__ void cp_wait() {
    asm volatile("cp.async.wait_group %0;" :: "n"(N));
}

// ---------------------------------------------------------------------------
// Kernel 1: per-(batch, token-chunk) partial mean-leaf vectors, disjoint STG.
// grid = B * NCHUNK = 256 blocks, 256 threads. Also zeroes `out`.
// ---------------------------------------------------------------------------
__global__ __launch_bounds__(256) void leaf_kernel(
    const float* __restrict__ x, const float* __restrict__ cuts,
    float* __restrict__ out)
{
    const int tid = threadIdx.x;
    const int gid = blockIdx.x * 256 + tid;    // 65536 >= 16000
    if (gid < BB * NC) out[gid] = 0.f;

    const int b     = blockIdx.x >> 4;
    const int chunk = blockIdx.x & 15;

    __shared__ float P[TOKC * 128];            // [tok][half*64 + u]  (16 KB)
    __shared__ float sx[TOKC * 12];
    __shared__ float sc[12];

    if (tid < 12) sc[tid] = cuts[tid];

    const float* xl = x + (size_t)(LL - 1) * BB * TT * HH
                        + ((size_t)b * TT + (size_t)chunk * TOKC) * HH;
    for (int i = tid; i < TOKC * 12; i += 256) sx[i] = xl[i];
    __syncthreads();

    // Phase A: factorized half-leaf products (8 contiguous outputs per task)
    {
        const int half = (tid >> 3) & 1;
        const int g    = tid & 7;
        const float* cr = sc + half * 6;
        const float c0 = cr[0], c1 = cr[1], c2 = cr[2];
        const float c3 = cr[3], c4 = cr[4], c5 = cr[5];
#pragma unroll
        for (int t2 = 0; t2 < 2; t2++) {
            const int tok = (tid >> 4) + t2 * 16;
            const float* xr = sx + tok * 12 + half * 6;
            const float x0 = xr[0], x1 = xr[1], x2 = xr[2];
            const float x3 = xr[3], x4 = xr[4], x5 = xr[5];
            const float F0 = (g & 4) ? fmaf(2.f, x0, -c0) : x0;
            const float F1 = (g & 2) ? fmaf(2.f, x1, -c1) : x1;
            const float F2 = (g & 1) ? fmaf(2.f, x2, -c2) : x2;
            const float p  = F0 * F1 * F2;
            const float b3 = fmaf(2.f, x3, -c3);
            const float a4 = x4, b4 = fmaf(2.f, x4, -c4);
            const float a5 = x5, b5 = fmaf(2.f, x5, -c5);
            const float m00 = a4 * a5, m01 = a4 * b5;
            const float m10 = b4 * a5, m11 = b4 * b5;
            const float q0 = p * x3, q1 = p * b3;
            float* dst = P + tok * 128 + half * 64 + g * 8;
            *(float4*)dst       = make_float4(q0 * m00, q0 * m01, q0 * m10, q0 * m11);
            *(float4*)(dst + 4) = make_float4(q1 * m00, q1 * m01, q1 * m10, q1 * m11);
        }
    }
    __syncthreads();

    // Phase B: rank-1 accumulation
    const int w = tid >> 5, lane = tid & 31;
    unsigned long long acc2[4][2];
#pragma unroll
    for (int p = 0; p < 4; p++) { acc2[p][0] = 0ull; acc2[p][1] = 0ull; }

#pragma unroll 4
    for (int tok = 0; tok < TOKC; tok++) {
        const float* Pr = P + tok * 128;
        const ulonglong2* ph = (const ulonglong2*)(Pr + 8 * w);
        const ulonglong2 h0 = ph[0];
        const ulonglong2 h1 = ph[1];
        const float plo0 = Pr[64 + lane];
        const float plo1 = Pr[64 + lane + 32];
        const unsigned long long pl0 = pk2(plo0, plo0);
        const unsigned long long pl1 = pk2(plo1, plo1);
        fma2(acc2[0][0], h0.x, pl0); fma2(acc2[0][1], h0.x, pl1);
        fma2(acc2[1][0], h0.y, pl0); fma2(acc2[1][1], h0.y, pl1);
        fma2(acc2[2][0], h1.x, pl0); fma2(acc2[2][1], h1.x, pl1);
        fma2(acc2[3][0], h1.y, pl0); fma2(acc2[3][1], h1.y, pl1);
    }

    const float s = 1.f / (float)TT;
    float* dst = g_part + ((size_t)(chunk * BB + b)) * NL;
#pragma unroll
    for (int p = 0; p < 4; p++) {
        float u0v0, u1v0, u0v1, u1v1;
        upk2(acc2[p][0], u0v0, u1v0);
        upk2(acc2[p][1], u0v1, u1v1);
        const int u0 = 8 * w + 2 * p;
        dst[u0 * 64 + lane]            = u0v0 * s;
        dst[u0 * 64 + lane + 32]       = u0v1 * s;
        dst[(u0 + 1) * 64 + lane]      = u1v0 * s;
        dst[(u0 + 1) * 64 + lane + 32] = u1v1 * s;
    }
}

// ---------------------------------------------------------------------------
// Kernel 2: out[16,1000] += avg[16,4096] @ score[4096,1000].
// grid = (64, 8) = 512 CTAs, 256 threads (8 warps): occupancy ~40%.
// CTA tile: 64 rows x 128 cols; thread = (col, batch-half) with 4 f32x2 accs.
// Rolling 3-stage cp.async pipeline (16 rows / 8 KB per stage).
// sA built inline by reducing the 16 L2-hot chunk partials.
// ---------------------------------------------------------------------------
#define G_LCH  64
#define G_CT   128
#define SROWS  16
#define NSTAGE 3
#define NITER  (G_LCH / SROWS)   // 4

__global__ __launch_bounds__(256) void gemm_out_kernel(
    const float* __restrict__ score, float* __restrict__ out)
{
    __shared__ float sS[NSTAGE * SROWS * G_CT];  // 24 KB (3 slots x 16 rows)
    __shared__ float sA[G_LCH * 16];             // 4 KB [l][b]

    const int tid = threadIdx.x;
    const int l0  = blockIdx.x * G_LCH;
    const int c0  = blockIdx.y * G_CT;
    const uint32_t sS_base = smem_u32(sS);

    // Stage issue: stage s (rows l0+s*16 .. +16) into slot s%3.
    auto issue_stage = [&](int s) {
        const int slot = s % NSTAGE;
#pragma unroll
        for (int t = 0; t < 2; t++) {
            const int k  = tid + t * 256;          // 0..511 16B-chunk id
            const int r  = k >> 5;                 // row in stage 0..15
            const int cc = k & 31;                 // 16B chunk in row
            const int col = c0 + cc * 4;
            const char* src = (const char*)score
                + (size_t)(l0 + s * SROWS + r) * (NC * 4) + (size_t)col * 4;
            const uint32_t dst = sS_base
                + (uint32_t)(((slot * SROWS + r) * G_CT + cc * 4) * 4);
            const int sz = (col + 4 <= NC) ? 16 : 0;
            cp_async16(dst, src, sz);
        }
        cp_commit();
    };

    // Prologue: 3 stages in flight
#pragma unroll
    for (int s = 0; s < NSTAGE; s++) issue_stage(s);

    // Build sA by reducing the 16 L2-hot chunk partials (float4):
    // 256 tasks = 16 batches x 16 leaf-quads, one per thread.
    {
        const int bb = tid >> 4;          // batch 0..15
        const int lq = tid & 15;          // leaf quad 0..15
        const float4* p = (const float4*)(g_part + (size_t)bb * NL + l0) + lq;
        float4 v = make_float4(0.f, 0.f, 0.f, 0.f);
#pragma unroll
        for (int ch = 0; ch < NCHUNK; ch++) {
            const float4 t = p[(size_t)ch * (BB * NL / 4)];
            v.x += t.x; v.y += t.y; v.z += t.z; v.w += t.w;
        }
        sA[(lq * 4 + 0) * 16 + bb] = v.x;
        sA[(lq * 4 + 1) * 16 + bb] = v.y;
        sA[(lq * 4 + 2) * 16 + bb] = v.z;
        sA[(lq * 4 + 3) * 16 + bb] = v.w;
    }

    unsigned long long acc[4];
#pragma unroll
    for (int p = 0; p < 4; p++) acc[p] = 0ull;

    const int ci    = tid & 127;          // column within tile
    const int bhalf = tid >> 7;           // batch half (0: b0-7, 1: b8-15)
    const int c     = c0 + ci;

    // Main loop: wait oldest stage, compute, refill freed slot (or dummy group)
#pragma unroll
    for (int it = 0; it < NITER; it++) {
        cp_wait<NSTAGE - 1>();
        __syncthreads();

        const int slot = it % NSTAGE;
        const float* sSrow = sS + slot * (SROWS * G_CT) + ci;
        const float* sArow = sA + (it * SROWS) * 16 + bhalf * 8;
#pragma unroll
        for (int r = 0; r < SROWS; r++) {
            const float sv = sSrow[r * G_CT];
            const unsigned long long ss = pk2(sv, sv);
            const ulonglong2 q  = *(const ulonglong2*)(sArow + r * 16);
            const ulonglong2 q2 = *(const ulonglong2*)(sArow + r * 16 + 4);
            fma2(acc[0], ss, q.x);  fma2(acc[1], ss, q.y);
            fma2(acc[2], ss, q2.x); fma2(acc[3], ss, q2.y);
        }
        __syncthreads();

        if (it + NSTAGE < NITER) issue_stage(it + NSTAGE);
        else cp_commit();                 // empty group keeps wait<2> accounting
    }

    if (c < NC) {
#pragma unroll
        for (int p = 0; p < 4; p++) {
            float blo, bhi;
            upk2(acc[p], blo, bhi);
            const int bb = bhalf * 8 + 2 * p;
            atomicAdd(out + bb * NC + c,       blo);
            atomicAdd(out + (bb + 1) * NC + c, bhi);
        }
    }
}

// ---------------------------------------------------------------------------
extern "C" void kernel_launch(void* const* d_in, const int* in_sizes, int n_in,
                              void* d_out, int out_size)
{
    const float* x     = (const float*)d_in[0];  // (2,16,512,12)
    const float* cuts  = (const float*)d_in[1];  // (12,1)
    const float* score = (const float*)d_in[2];  // (4096,1000)
    float* out = (float*)d_out;                  // (16,1000)

    leaf_kernel<<<BB * NCHUNK, 256>>>(x, cuts, out);
    dim3 g3(NL / G_LCH, (NC + G_CT - 1) / G_CT);   // (64, 8)
    gemm_out_kernel<<<g3, 256>>>(score, out);
}

// round 17
// speedup vs baseline: 1.2358x; 1.1170x over previous
#include <cuda_runtime.h>
#include <cstdint>

// Problem constants
#define LL 2
#define BB 16
#define TT 512
#define HH 12
#define NL 4096   // (1+1)^12 leaves
#define NC 1000
#define NCHUNK 8  // token chunks per batch
#define TOKC 64   // tokens per chunk

// Scratch: [chunk][batch][leaf]  (2 MB)
__device__ float g_part[NCHUNK * BB * NL];

// ---- f32x2 helpers ---------------------------------------------------------
__device__ __forceinline__ unsigned long long pk2(float x, float y) {
    unsigned long long r;
    asm("mov.b64 %0, {%1, %2};" : "=l"(r) : "f"(x), "f"(y));
    return r;
}
__device__ __forceinline__ void fma2(unsigned long long& d,
                                     unsigned long long a,
                                     unsigned long long b) {
    asm("fma.rn.f32x2 %0, %1, %2, %0;" : "+l"(d) : "l"(a), "l"(b));
}
__device__ __forceinline__ void upk2(unsigned long long v, float& lo, float& hi) {
    asm("mov.b64 {%0, %1}, %2;" : "=f"(lo), "=f"(hi) : "l"(v));
}

// ---- cp.async helpers ------------------------------------------------------
__device__ __forceinline__ uint32_t smem_u32(const void* p) {
    uint32_t a;
    asm("{ .reg .u64 t; cvta.to.shared.u64 t, %1; cvt.u32.u64 %0, t; }"
        : "=r"(a) : "l"(p));
    return a;
}
__device__ __forceinline__ void cp_async16(uint32_t dst, const void* src, int sz) {
    asm volatile("cp.async.cg.shared.global [%0], [%1], 16, %2;"
                 :: "r"(dst), "l"(src), "r"(sz));
}
__device__ __forceinline__ void cp_commit() {
    asm volatile("cp.async.commit_group;");
}
template <int N> __device__ __forceinline__ void cp_wait() {
    asm volatile("cp.async.wait_group %0;" :: "n"(N));
}

// ---------------------------------------------------------------------------
// Kernel 1: leaf partials. grid = B*8 = 128 CTAs (SINGLE WAVE), 512 threads
// (16 warps/SM everywhere). Each CTA: one (batch, 64-token chunk).
// Phase B: warp w owns u in [4w, 4w+4); per token 1 broadcast LDS.128 +
// 2 scalar LDS + 4 fma2. Also zeroes `out`.
// ---------------------------------------------------------------------------
__global__ __launch_bounds__(512) void leaf_kernel(
    const float* __restrict__ x, const float* __restrict__ cuts,
    float* __restrict__ out)
{
    const int tid = threadIdx.x;
    const int gid = blockIdx.x * 512 + tid;    // 128*512 = 65536 >= 16000
    if (gid < BB * NC) out[gid] = 0.f;

    const int b     = blockIdx.x >> 3;         // batch
    const int chunk = blockIdx.x & 7;          // token chunk of 64

    __shared__ float P[TOKC * 128];            // [tok][half*64 + u]  (32 KB)
    __shared__ float sx[TOKC * 12];
    __shared__ float sc[12];

    if (tid < 12) sc[tid] = cuts[tid];

    const float* xl = x + (size_t)(LL - 1) * BB * TT * HH
                        + ((size_t)b * TT + (size_t)chunk * TOKC) * HH;
    for (int i = tid; i < TOKC * 12; i += 512) sx[i] = xl[i];
    __syncthreads();

    // Phase A: 1024 tasks (tok, half, g); 512 threads x 2 (tok +0, +32).
    {
        const int half = (tid >> 3) & 1;
        const int g    = tid & 7;
        const float* cr = sc + half * 6;
        const float c0 = cr[0], c1 = cr[1], c2 = cr[2];
        const float c3 = cr[3], c4 = cr[4], c5 = cr[5];
#pragma unroll
        for (int t2 = 0; t2 < 2; t2++) {
            const int tok = (tid >> 4) + t2 * 32;
            const float* xr = sx + tok * 12 + half * 6;
            const float x0 = xr[0], x1 = xr[1], x2 = xr[2];
            const float x3 = xr[3], x4 = xr[4], x5 = xr[5];
            const float F0 = (g & 4) ? fmaf(2.f, x0, -c0) : x0;
            const float F1 = (g & 2) ? fmaf(2.f, x1, -c1) : x1;
            const float F2 = (g & 1) ? fmaf(2.f, x2, -c2) : x2;
            const float p  = F0 * F1 * F2;
            const float b3 = fmaf(2.f, x3, -c3);
            const float a4 = x4, b4 = fmaf(2.f, x4, -c4);
            const float a5 = x5, b5 = fmaf(2.f, x5, -c5);
            const float m00 = a4 * a5, m01 = a4 * b5;
            const float m10 = b4 * a5, m11 = b4 * b5;
            const float q0 = p * x3, q1 = p * b3;
            float* dst = P + tok * 128 + half * 64 + g * 8;
            *(float4*)dst       = make_float4(q0 * m00, q0 * m01, q0 * m10, q0 * m11);
            *(float4*)(dst + 4) = make_float4(q1 * m00, q1 * m01, q1 * m10, q1 * m11);
        }
    }
    __syncthreads();

    // Phase B: rank-1 accumulation; 16 warps, warp w owns u in [4w, 4w+4).
    const int w = tid >> 5, lane = tid & 31;
    unsigned long long acc2[2][2];   // [u-pair][v-half]
    acc2[0][0] = 0ull; acc2[0][1] = 0ull;
    acc2[1][0] = 0ull; acc2[1][1] = 0ull;

#pragma unroll 8
    for (int tok = 0; tok < TOKC; tok++) {
        const float* Pr = P + tok * 128;
        const ulonglong2 h = *(const ulonglong2*)(Pr + 4 * w);  // u 4w..4w+3
        const float plo0 = Pr[64 + lane];
        const float plo1 = Pr[96 + lane];
        const unsigned long long pl0 = pk2(plo0, plo0);
        const unsigned long long pl1 = pk2(plo1, plo1);
        fma2(acc2[0][0], h.x, pl0); fma2(acc2[0][1], h.x, pl1);
        fma2(acc2[1][0], h.y, pl0); fma2(acc2[1][1], h.y, pl1);
    }

    const float s = 1.f / (float)TT;
    float* dst = g_part + ((size_t)(chunk * BB + b)) * NL;
#pragma unroll
    for (int p = 0; p < 2; p++) {
        float u0v0, u1v0, u0v1, u1v1;
        upk2(acc2[p][0], u0v0, u1v0);
        upk2(acc2[p][1], u0v1, u1v1);
        const int u0 = 4 * w + 2 * p;
        dst[u0 * 64 + lane]            = u0v0 * s;
        dst[u0 * 64 + lane + 32]       = u0v1 * s;
        dst[(u0 + 1) * 64 + lane]      = u1v0 * s;
        dst[(u0 + 1) * 64 + lane + 32] = u1v1 * s;
    }
}

// ---------------------------------------------------------------------------
// Kernel 2: out[16,1000] += avg[16,4096] @ score[4096,1000].
// grid = (64, 8) = 512 CTAs, 256 threads. Rolling 3-stage cp.async pipeline.
// sA built inline by reducing the 8 L2-hot chunk partials.  (R16 config.)
// ---------------------------------------------------------------------------
#define G_LCH  64
#define G_CT   128
#define SROWS  16
#define NSTAGE 3
#define NITER  (G_LCH / SROWS)   // 4

__global__ __launch_bounds__(256) void gemm_out_kernel(
    const float* __restrict__ score, float* __restrict__ out)
{
    __shared__ float sS[NSTAGE * SROWS * G_CT];  // 24 KB
    __shared__ float sA[G_LCH * 16];             // 4 KB [l][b]

    const int tid = threadIdx.x;
    const int l0  = blockIdx.x * G_LCH;
    const int c0  = blockIdx.y * G_CT;
    const uint32_t sS_base = smem_u32(sS);

    auto issue_stage = [&](int s) {
        const int slot = s % NSTAGE;
#pragma unroll
        for (int t = 0; t < 2; t++) {
            const int k  = tid + t * 256;
            const int r  = k >> 5;
            const int cc = k & 31;
            const int col = c0 + cc * 4;
            const char* src = (const char*)score
                + (size_t)(l0 + s * SROWS + r) * (NC * 4) + (size_t)col * 4;
            const uint32_t dst = sS_base
                + (uint32_t)(((slot * SROWS + r) * G_CT + cc * 4) * 4);
            const int sz = (col + 4 <= NC) ? 16 : 0;
            cp_async16(dst, src, sz);
        }
        cp_commit();
    };

#pragma unroll
    for (int s = 0; s < NSTAGE; s++) issue_stage(s);

    // Build sA by reducing the 8 L2-hot chunk partials (float4).
    {
        const int bb = tid >> 4;          // batch 0..15
        const int lq = tid & 15;          // leaf quad 0..15
        const float4* p = (const float4*)(g_part + (size_t)bb * NL + l0) + lq;
        float4 v = make_float4(0.f, 0.f, 0.f, 0.f);
#pragma unroll
        for (int ch = 0; ch < NCHUNK; ch++) {
            const float4 t = p[(size_t)ch * (BB * NL / 4)];
            v.x += t.x; v.y += t.y; v.z += t.z; v.w += t.w;
        }
        sA[(lq * 4 + 0) * 16 + bb] = v.x;
        sA[(lq * 4 + 1) * 16 + bb] = v.y;
        sA[(lq * 4 + 2) * 16 + bb] = v.z;
        sA[(lq * 4 + 3) * 16 + bb] = v.w;
    }

    unsigned long long acc[4];
#pragma unroll
    for (int p = 0; p < 4; p++) acc[p] = 0ull;

    const int ci    = tid & 127;
    const int bhalf = tid >> 7;
    const int c     = c0 + ci;

#pragma unroll
    for (int it = 0; it < NITER; it++) {
        cp_wait<NSTAGE - 1>();
        __syncthreads();

        const int slot = it % NSTAGE;
        const float* sSrow = sS + slot * (SROWS * G_CT) + ci;
        const float* sArow = sA + (it * SROWS) * 16 + bhalf * 8;
#pragma unroll
        for (int r = 0; r < SROWS; r++) {
            const float sv = sSrow[r * G_CT];
            const unsigned long long ss = pk2(sv, sv);
            const ulonglong2 q  = *(const ulonglong2*)(sArow + r * 16);
            const ulonglong2 q2 = *(const ulonglong2*)(sArow + r * 16 + 4);
            fma2(acc[0], ss, q.x);  fma2(acc[1], ss, q.y);
            fma2(acc[2], ss, q2.x); fma2(acc[3], ss, q2.y);
        }
        __syncthreads();

        if (it + NSTAGE < NITER) issue_stage(it + NSTAGE);
        else cp_commit();
    }

    if (c < NC) {
#pragma unroll
        for (int p = 0; p < 4; p++) {
            float blo, bhi;
            upk2(acc[p], blo, bhi);
            const int bb = bhalf * 8 + 2 * p;
            atomicAdd(out + bb * NC + c,       blo);
            atomicAdd(out + (bb + 1) * NC + c, bhi);
        }
    }
}

// ---------------------------------------------------------------------------
extern "C" void kernel_launch(void* const* d_in, const int* in_sizes, int n_in,
                              void* d_out, int out_size)
{
    const float* x     = (const float*)d_in[0];  // (2,16,512,12)
    const float* cuts  = (const float*)d_in[1];  // (12,1)
    const float* score = (const float*)d_in[2];  // (4096,1000)
    float* out = (float*)d_out;                  // (16,1000)

    leaf_kernel<<<BB * NCHUNK, 512>>>(x, cuts, out);
    dim3 g3(NL / G_LCH, (NC + G_CT - 1) / G_CT);   // (64, 8)
    gemm_out_kernel<<<g3, 256>>>(score, out);
}